// round 10
// baseline (speedup 1.0000x reference)
#include <cuda_runtime.h>
#include <cuda_fp16.h>
#include <math.h>
#include <cstdint>

// Problem dims (fixed by dataset)
#define B_DIM 8192
#define I_DIM 1024
#define H_DIM 1024
#define N4    4096
#define K2    2048   // I+H

// ---------------- scratch (device globals; allocation-free) ----------------
__device__ __half g_xhi [(size_t)B_DIM * I_DIM];     // fp16(x)
__device__ __half g_ahi [(size_t)B_DIM * K2];        // fp16([xmod | hx])
__device__ __half g_wmT [(size_t)H_DIM * I_DIM];     // fp16(Wm^T) [H, I]
__device__ __half g_wT  [(size_t)N4 * K2];           // fp16(W^T)  [4H, I+H]
__device__ __half g_im  [(size_t)B_DIM * H_DIM];     // fp16(x@Wm + bm)
__device__ __half g_gates[(size_t)B_DIM * N4];       // fp16 pre-LN gates

__device__ __forceinline__ float sigmoidf_(float z) {
    return 1.0f / (1.0f + __expf(-z));
}
__device__ __forceinline__ uint32_t smem_u32(const void* p) {
    uint32_t a;
    asm("{ .reg .u64 t; cvta.to.shared.u64 t, %1; cvt.u32.u64 %0, t; }"
        : "=r"(a) : "l"(p));
    return a;
}
__device__ __forceinline__ uint32_t sw128(uint32_t off) {
    return off ^ ((off >> 3) & 0x70);
}
__device__ __forceinline__ uint32_t pack_half2(float a, float b) {
    __half2 h = __floats2half2_rn(a, b);
    return *reinterpret_cast<uint32_t*>(&h);
}

// ---------------------------------------------------------------------------
// fp16 GEMM via mma.sync.m16n8k16, fp16 output.
// C[M,N] = fp16(A @ B^T + bias).
// CTA tile 128x64, KC=64, 256 thr (8 warps: 2M x 4N, warp tile 64x16),
// 3-stage cp.async, one __syncthreads per chunk, occupancy 3 (24 warps/SM).
// ---------------------------------------------------------------------------
#define TM 128
#define TN 64
#define KC 64
#define A_STG 16384                    // 128 rows x 128B
#define B_STG 8192                     // 64 rows x 128B
#define STG   (A_STG + B_STG)          // 24KB per stage
#define NSTAGE 3
#define GEMM_SMEM (NSTAGE * STG)       // 72KB

__global__ __launch_bounds__(256, 3)
void hgemm_mma(const __half* __restrict__ A, const __half* __restrict__ BT,
               const float* __restrict__ bias, __half* __restrict__ C,
               int M, int N, int K)
{
    extern __shared__ char smem_raw[];
    const uint32_t SM = smem_u32(smem_raw);

    const int tid  = threadIdx.x;
    const int wid  = tid >> 5;
    const int lane = tid & 31;
    const int wm   = (wid & 1) * 64;           // 2 M-warps over 128
    const int wn   = (wid >> 1) * 16;          // 4 N-warps over 64
    const int m0   = blockIdx.y * TM;
    const int n0   = blockIdx.x * TN;

    const int nc = K / KC;

    auto load_chunk = [&](int c, int stage) {
        const int kk = c * KC;
        const __half* Ag = A  + (size_t)m0 * K + kk;
        const __half* Bg = BT + (size_t)n0 * K + kk;
        const uint32_t sa = SM + stage * STG;
        const uint32_t sb = sa + A_STG;
#pragma unroll
        for (int t = 0; t < 4; t++) {              // A: 1024 x 16B
            int idx = tid + 256 * t;
            int rr = idx >> 3, ii = idx & 7;
            uint32_t off = sw128((uint32_t)(rr * 128 + ii * 16));
            asm volatile("cp.async.cg.shared.global [%0], [%1], 16;"
                         :: "r"(sa + off), "l"(Ag + (size_t)rr * K + ii * 8));
        }
#pragma unroll
        for (int t = 0; t < 2; t++) {              // B: 512 x 16B
            int idx = tid + 256 * t;
            int rr = idx >> 3, ii = idx & 7;
            uint32_t off = sw128((uint32_t)(rr * 128 + ii * 16));
            asm volatile("cp.async.cg.shared.global [%0], [%1], 16;"
                         :: "r"(sb + off), "l"(Bg + (size_t)rr * K + ii * 8));
        }
        asm volatile("cp.async.commit_group;" ::: "memory");
    };

    float acc[4][2][4];
#pragma unroll
    for (int mi = 0; mi < 4; mi++)
#pragma unroll
        for (int ni = 0; ni < 2; ni++)
#pragma unroll
            for (int q = 0; q < 4; q++) acc[mi][ni][q] = 0.0f;

    load_chunk(0, 0);
    load_chunk(1, 1);

    const int aRow  = wm + (lane & 15);        // + mi*16
    const int bRow  = wn + (lane & 15);        // single n16 tile
    const int colHB = (lane >> 4) * 16;

    for (int c = 0; c < nc; c++) {
        if (c + 1 < nc) asm volatile("cp.async.wait_group 1;" ::: "memory");
        else            asm volatile("cp.async.wait_group 0;" ::: "memory");
        __syncthreads();
        if (c + 2 < nc) load_chunk(c + 2, (c + 2) % NSTAGE);

        const uint32_t sa = SM + (c % NSTAGE) * STG;
        const uint32_t sb = sa + A_STG;

#pragma unroll
        for (int ks = 0; ks < KC / 16; ks++) {
            uint32_t a[4][4], b[4];
#pragma unroll
            for (int mi = 0; mi < 4; mi++) {
                uint32_t addr = sa + sw128((uint32_t)((aRow + mi * 16) * 128 + ks * 32 + colHB));
                asm volatile("ldmatrix.sync.aligned.m8n8.x4.shared.b16 {%0,%1,%2,%3}, [%4];"
                             : "=r"(a[mi][0]), "=r"(a[mi][1]), "=r"(a[mi][2]), "=r"(a[mi][3])
                             : "r"(addr));
            }
            {
                uint32_t addr = sb + sw128((uint32_t)(bRow * 128 + ks * 32 + colHB));
                asm volatile("ldmatrix.sync.aligned.m8n8.x4.shared.b16 {%0,%1,%2,%3}, [%4];"
                             : "=r"(b[0]), "=r"(b[1]), "=r"(b[2]), "=r"(b[3])
                             : "r"(addr));
            }
#pragma unroll
            for (int mi = 0; mi < 4; mi++)
#pragma unroll
                for (int ni = 0; ni < 2; ni++) {
                    asm volatile(
                        "mma.sync.aligned.m16n8k16.row.col.f32.f16.f16.f32 "
                        "{%0,%1,%2,%3}, {%4,%5,%6,%7}, {%8,%9}, {%0,%1,%2,%3};"
                        : "+f"(acc[mi][ni][0]), "+f"(acc[mi][ni][1]),
                          "+f"(acc[mi][ni][2]), "+f"(acc[mi][ni][3])
                        : "r"(a[mi][0]), "r"(a[mi][1]), "r"(a[mi][2]), "r"(a[mi][3]),
                          "r"(b[ni]), "r"(b[ni + 2]));
                }
        }
    }

    // Store fp16: lane l owns (row = mi*16 + l/4 (+8), col = ni*8 + (l%4)*2)
    const int r0 = m0 + wm + (lane >> 2);
    const int c0 = n0 + wn + (lane & 3) * 2;
#pragma unroll
    for (int mi = 0; mi < 4; mi++) {
#pragma unroll
        for (int ni = 0; ni < 2; ni++) {
            int col = c0 + ni * 8;
            float bx = bias[col], by = bias[col + 1];
            uint32_t h0 = pack_half2(acc[mi][ni][0] + bx, acc[mi][ni][1] + by);
            uint32_t h1 = pack_half2(acc[mi][ni][2] + bx, acc[mi][ni][3] + by);
            *(uint32_t*)(C + (size_t)(r0 + mi * 16) * N + col) = h0;
            *(uint32_t*)(C + (size_t)(r0 + mi * 16 + 8) * N + col) = h1;
        }
    }
}

// ---------------------------------------------------------------------------
// Merged transpose+fp16 for both weight matrices (one launch).
// ---------------------------------------------------------------------------
#define WM_TILES ((H_DIM / 32) * (I_DIM / 32))   // 1024

__global__ __launch_bounds__(256)
void transpose_both(const float* __restrict__ W, const float* __restrict__ Wm)
{
    __shared__ float t[32][33];
    const int tx = threadIdx.x, ty = threadIdx.y;
    int bid = blockIdx.x;
    if (bid < WM_TILES) {
        int cx = bid & (H_DIM / 32 - 1), ry = bid / (H_DIM / 32);
        int r0 = ry * 32, c0 = cx * 32;
        for (int i = ty; i < 32; i += 8)
            t[i][tx] = Wm[(size_t)(r0 + i) * H_DIM + c0 + tx];
        __syncthreads();
        for (int j = ty; j < 32; j += 8)
            g_wmT[(size_t)(c0 + j) * I_DIM + r0 + tx] = __float2half_rn(t[tx][j]);
    } else {
        bid -= WM_TILES;
        int cx = bid & (N4 / 32 - 1), ry = bid / (N4 / 32);
        int r0 = ry * 32, c0 = cx * 32;
        for (int i = ty; i < 32; i += 8)
            t[i][tx] = W[(size_t)(r0 + i) * N4 + c0 + tx];
        __syncthreads();
        for (int j = ty; j < 32; j += 8)
            g_wT[(size_t)(c0 + j) * K2 + r0 + tx] = __float2half_rn(t[tx][j]);
    }
}

// ---------------------------------------------------------------------------
// Vectorized activation rounding: x -> g_xhi; hx -> g_ahi cols [1024,2048)
// ---------------------------------------------------------------------------
__global__ __launch_bounds__(256)
void split_acts(const float* __restrict__ x, const float* __restrict__ hx)
{
    const int Q1 = (B_DIM * I_DIM) / 4;
    const int total = Q1 + (B_DIM * H_DIM) / 4;
    for (int q = blockIdx.x * blockDim.x + threadIdx.x; q < total;
         q += gridDim.x * blockDim.x) {
        if (q < Q1) {
            float4 v = ((const float4*)x)[q];
            uint2 o;
            o.x = pack_half2(v.x, v.y);
            o.y = pack_half2(v.z, v.w);
            ((uint2*)g_xhi)[q] = o;
        } else {
            int j = q - Q1;
            int r = j >> 8, c4 = j & 255;
            float4 v = ((const float4*)hx)[j];
            uint2 o;
            o.x = pack_half2(v.x, v.y);
            o.y = pack_half2(v.z, v.w);
            *(uint2*)(g_ahi + (size_t)r * K2 + 1024 + c4 * 4) = o;
        }
    }
}

// ---------------------------------------------------------------------------
__device__ __forceinline__ void block_reduce(float* vals, int n, float* sh, float* outp)
{
    const int lane = threadIdx.x & 31;
    const int warp = threadIdx.x >> 5;
    const int nw   = blockDim.x >> 5;
    for (int q = 0; q < n; q++) {
        float v = vals[q];
#pragma unroll
        for (int o = 16; o > 0; o >>= 1) v += __shfl_xor_sync(0xffffffffu, v, o);
        if (lane == 0) sh[warp * 8 + q] = v;
    }
    __syncthreads();
    if (warp < n) {
        float v = (lane < nw) ? sh[lane * 8 + warp] : 0.0f;
#pragma unroll
        for (int o = 16; o > 0; o >>= 1) v += __shfl_xor_sync(0xffffffffu, v, o);
        if (lane == 0) outp[warp] = v;
    }
    __syncthreads();
}

// ---------------------------------------------------------------------------
// attn = sigmoid(cos(im, hx)); write fp16((1+attn)*x) into A cols [0,1024)
// ---------------------------------------------------------------------------
__global__ __launch_bounds__(256)
void attn_scale_kernel(const float* __restrict__ x, const float* __restrict__ hx)
{
    __shared__ float sh[32 * 8];
    __shared__ float outp[8];
    const int r = blockIdx.x;
    const int t = threadIdx.x;

    uint2 iv = ((const uint2*)(g_im + (size_t)r * H_DIM))[t];
    __half2 i01 = *reinterpret_cast<__half2*>(&iv.x);
    __half2 i23 = *reinterpret_cast<__half2*>(&iv.y);
    float2 f01 = __half22float2(i01);
    float2 f23 = __half22float2(i23);
    float4 b4 = ((const float4*)(hx + (size_t)r * H_DIM))[t];

    float dot = f01.x * b4.x + f01.y * b4.y + f23.x * b4.z + f23.y * b4.w;
    float s1  = f01.x * f01.x + f01.y * f01.y + f23.x * f23.x + f23.y * f23.y;
    float s2  = b4.x * b4.x + b4.y * b4.y + b4.z * b4.z + b4.w * b4.w;

    float vals[3] = {dot, s1, s2};
    block_reduce(vals, 3, sh, outp);

    float na = fmaxf(sqrtf(outp[1]), 1e-6f);
    float nb = fmaxf(sqrtf(outp[2]), 1e-6f);
    float scale = 1.0f + sigmoidf_(outp[0] / (na * nb));

    float4 xv = ((const float4*)(x + (size_t)r * I_DIM))[t];
    uint2 o;
    o.x = pack_half2(xv.x * scale, xv.y * scale);
    o.y = pack_half2(xv.z * scale, xv.w * scale);
    *(uint2*)(g_ahi + (size_t)r * K2 + t * 4) = o;
}

// ---------------------------------------------------------------------------
// Fused epilogue: 4x LN + act, cell update, cosine gate, outputs (fp32 out)
// ---------------------------------------------------------------------------
__global__ __launch_bounds__(1024)
void epilogue_kernel(const float* __restrict__ cx, const float* __restrict__ gammas,
                     const float* __restrict__ betas, float* __restrict__ out)
{
    __shared__ float sh[32 * 8];
    __shared__ float outp[8];
    const int r = blockIdx.x;
    const int j = threadIdx.x;
    const __half* grow = g_gates + (size_t)r * N4;

    float v[4];
    v[0] = __half2float(grow[j]);
    v[1] = __half2float(grow[j + 1024]);
    v[2] = __half2float(grow[j + 2048]);
    v[3] = __half2float(grow[j + 3072]);

    float vals[8] = {v[0], v[1], v[2], v[3],
                     v[0]*v[0], v[1]*v[1], v[2]*v[2], v[3]*v[3]};
    block_reduce(vals, 8, sh, outp);

    const float invH = 1.0f / 1024.0f;
    float act[4];
#pragma unroll
    for (int q = 0; q < 4; q++) {
        float mu  = outp[q] * invH;
        float var = outp[q + 4] * invH - mu * mu;
        act[q] = (v[q] - mu) * rsqrtf(var + 1e-5f) * gammas[q * 1024 + j]
                 + betas[q * 1024 + j];
    }
    float i_g = sigmoidf_(act[0]);
    float f_g = sigmoidf_(act[1]);
    float g_g = tanhf(act[2]);
    float o_g = sigmoidf_(act[3]);

    float cxn = fmaf(f_g, cx[(size_t)r * 1024 + j], i_g * g_g);
    float hxn = o_g * tanhf(cxn);

    float vals2[3] = {hxn * cxn, hxn * hxn, cxn * cxn};
    block_reduce(vals2, 3, sh, outp);

    float na = fmaxf(sqrtf(outp[1]), 1e-6f);
    float nb = fmaxf(sqrtf(outp[2]), 1e-6f);
    float gc = sigmoidf_((outp[0] / (na * nb) + 1.0f) * 0.5f);

    out[(size_t)r * 1024 + j] = hxn * (1.0f + gc);
    out[(size_t)B_DIM * 1024 + (size_t)r * 1024 + j] = cxn;
}

// ---------------------------------------------------------------------------
extern "C" void kernel_launch(void* const* d_in, const int* in_sizes, int n_in,
                              void* d_out, int out_size)
{
    const float* x      = (const float*)d_in[0];
    const float* hx     = (const float*)d_in[1];
    const float* cx     = (const float*)d_in[2];
    const float* W      = (const float*)d_in[3];   // [2048, 4096]
    const float* b      = (const float*)d_in[4];   // [4096]
    const float* Wm     = (const float*)d_in[5];   // [1024, 1024]
    const float* bm     = (const float*)d_in[6];   // [1024]
    const float* gammas = (const float*)d_in[7];
    const float* betas  = (const float*)d_in[8];
    float* out = (float*)d_out;

    __half *p_xhi, *p_ahi, *p_wmT, *p_wT, *p_im, *p_gates;
    cudaGetSymbolAddress((void**)&p_xhi,   g_xhi);
    cudaGetSymbolAddress((void**)&p_ahi,   g_ahi);
    cudaGetSymbolAddress((void**)&p_wmT,   g_wmT);
    cudaGetSymbolAddress((void**)&p_wT,    g_wT);
    cudaGetSymbolAddress((void**)&p_im,    g_im);
    cudaGetSymbolAddress((void**)&p_gates, g_gates);

    cudaFuncSetAttribute(hgemm_mma, cudaFuncAttributeMaxDynamicSharedMemorySize,
                         GEMM_SMEM);

    // (1) weight transposes + fp16
    transpose_both<<<WM_TILES + (N4 / 32) * (K2 / 32), dim3(32, 8)>>>(W, Wm);

    // (2) activation fp16 rounding
    split_acts<<<4096, 256>>>(x, hx);

    // (3) GEMM1: im = fp16(x @ Wm + bm)  [8192,1024]
    hgemm_mma<<<dim3(H_DIM / TN, B_DIM / TM), 256, GEMM_SMEM>>>(
        p_xhi, p_wmT, bm, p_im, B_DIM, H_DIM, I_DIM);

    // (4) attn gate; write fp16 x_mod into A cols [0,1024)
    attn_scale_kernel<<<B_DIM, 256>>>(x, hx);

    // (5) GEMM2: gates = fp16([xmod|hx] @ W + b)  [8192,4096]
    hgemm_mma<<<dim3(N4 / TN, B_DIM / TM), 256, GEMM_SMEM>>>(
        p_ahi, p_wT, b, p_gates, B_DIM, N4, K2);

    // (6) fused LN/activation/cell/cosine epilogue
    epilogue_kernel<<<B_DIM, 1024>>>(cx, gammas, betas, out);
}

// round 11
// speedup vs baseline: 1.0060x; 1.0060x over previous
#include <cuda_runtime.h>
#include <cuda_fp16.h>
#include <math.h>
#include <cstdint>

// Problem dims (fixed by dataset)
#define B_DIM 8192
#define I_DIM 1024
#define H_DIM 1024
#define N4    4096
#define K2    2048   // I+H
#define N_A   5120   // Wm(1024) + W_top(4096) fused N for GEMM_A
#define KDIM  1024   // K for both GEMMs

// ---------------- scratch (device globals; allocation-free) ----------------
__device__ __half g_axh [(size_t)B_DIM * K2];        // [fp16(x) | fp16(hx)]
__device__ __half g_bt  [(size_t)(N_A + N4) * KDIM]; // [Wm^T; W_top^T; W_bot^T]
__device__ __half g_c1  [(size_t)B_DIM * N_A];       // x @ [Wm | W_top]
__device__ __half g_c2  [(size_t)B_DIM * N4];        // hx @ W_bot

__device__ __forceinline__ float sigmoidf_(float z) {
    return 1.0f / (1.0f + __expf(-z));
}
__device__ __forceinline__ uint32_t smem_u32(const void* p) {
    uint32_t a;
    asm("{ .reg .u64 t; cvta.to.shared.u64 t, %1; cvt.u32.u64 %0, t; }"
        : "=r"(a) : "l"(p));
    return a;
}
__device__ __forceinline__ uint32_t sw128(uint32_t off) {
    return off ^ ((off >> 3) & 0x70);
}
__device__ __forceinline__ uint32_t pack_half2(float a, float b) {
    __half2 h = __floats2half2_rn(a, b);
    return *reinterpret_cast<uint32_t*>(&h);
}

// ---------------------------------------------------------------------------
// Fused dual-GEMM (R9 engine, pinned): both sub-GEMMs K=1024, lda=2048.
//   bid <  2560 : C1[m,n] = x  @ [Wm|W_top]^T   (N=5120)
//   bid >= 2560 : C2[m,n] = hx @ W_bot^T        (N=4096)
// CTA tile 128x128, KC=64, 256 thr (8 warps, 2Mx4N warp tile 64x32),
// 3-stage cp.async, one __syncthreads per chunk. fp16 out, no bias.
// ---------------------------------------------------------------------------
#define TM 128
#define TN 128
#define KC 64
#define A_STG 16384
#define B_STG 16384
#define STG   (A_STG + B_STG)          // 32KB per stage
#define NSTAGE 3
#define GEMM_SMEM (NSTAGE * STG)       // 96KB
#define GRID_A (( N_A / TN) * (B_DIM / TM))   // 40*64 = 2560
#define GRID_B (( N4  / TN) * (B_DIM / TM))   // 32*64 = 2048

__global__ __launch_bounds__(256, 2)
void hgemm_dual()
{
    extern __shared__ char smem_raw[];
    const uint32_t SM = smem_u32(smem_raw);

    const int tid  = threadIdx.x;
    const int wid  = tid >> 5;
    const int lane = tid & 31;
    const int wm   = (wid & 1) * 64;
    const int wn   = (wid >> 1) * 32;

    // decode sub-problem
    int bid = blockIdx.x;
    const __half* A;  const __half* BT;  __half* C;
    int Ncols, m0, n0;
    if (bid < GRID_A) {
        int nx = bid % (N_A / TN), my = bid / (N_A / TN);
        A = g_axh;                 // x half (cols 0-1023)
        BT = g_bt;                 // rows 0-5119
        C = g_c1;  Ncols = N_A;
        m0 = my * TM;  n0 = nx * TN;
    } else {
        bid -= GRID_A;
        int nx = bid % (N4 / TN), my = bid / (N4 / TN);
        A = g_axh + 1024;          // hx half (cols 1024-2047)
        BT = g_bt + (size_t)N_A * KDIM;  // W_bot^T rows
        C = g_c2;  Ncols = N4;
        m0 = my * TM;  n0 = nx * TN;
    }

    const int nc = KDIM / KC;      // 16

    auto load_chunk = [&](int c, int stage) {
        const int kk = c * KC;
        const __half* Ag = A  + (size_t)m0 * K2 + kk;       // lda = 2048
        const __half* Bg = BT + (size_t)n0 * KDIM + kk;     // ldb = 1024
        const uint32_t sa = SM + stage * STG;
        const uint32_t sb = sa + A_STG;
#pragma unroll
        for (int t = 0; t < 4; t++) {
            int idx = tid + 256 * t;
            int rr = idx >> 3, ii = idx & 7;
            uint32_t off = sw128((uint32_t)(rr * 128 + ii * 16));
            asm volatile("cp.async.cg.shared.global [%0], [%1], 16;"
                         :: "r"(sa + off), "l"(Ag + (size_t)rr * K2 + ii * 8));
            asm volatile("cp.async.cg.shared.global [%0], [%1], 16;"
                         :: "r"(sb + off), "l"(Bg + (size_t)rr * KDIM + ii * 8));
        }
        asm volatile("cp.async.commit_group;" ::: "memory");
    };

    float acc[4][4][4];
#pragma unroll
    for (int mi = 0; mi < 4; mi++)
#pragma unroll
        for (int ni = 0; ni < 4; ni++)
#pragma unroll
            for (int q = 0; q < 4; q++) acc[mi][ni][q] = 0.0f;

    load_chunk(0, 0);
    load_chunk(1, 1);

    const int aRow  = wm + (lane & 15);
    const int bRow  = wn + (lane & 15);
    const int colHB = (lane >> 4) * 16;

    for (int c = 0; c < nc; c++) {
        if (c + 1 < nc) asm volatile("cp.async.wait_group 1;" ::: "memory");
        else            asm volatile("cp.async.wait_group 0;" ::: "memory");
        __syncthreads();
        if (c + 2 < nc) load_chunk(c + 2, (c + 2) % NSTAGE);

        const uint32_t sa = SM + (c % NSTAGE) * STG;
        const uint32_t sb = sa + A_STG;

#pragma unroll
        for (int ks = 0; ks < KC / 16; ks++) {
            uint32_t a[4][4], b[2][4];
#pragma unroll
            for (int mi = 0; mi < 4; mi++) {
                uint32_t addr = sa + sw128((uint32_t)((aRow + mi * 16) * 128 + ks * 32 + colHB));
                asm volatile("ldmatrix.sync.aligned.m8n8.x4.shared.b16 {%0,%1,%2,%3}, [%4];"
                             : "=r"(a[mi][0]), "=r"(a[mi][1]), "=r"(a[mi][2]), "=r"(a[mi][3])
                             : "r"(addr));
            }
#pragma unroll
            for (int nj = 0; nj < 2; nj++) {
                uint32_t addr = sb + sw128((uint32_t)((bRow + nj * 16) * 128 + ks * 32 + colHB));
                asm volatile("ldmatrix.sync.aligned.m8n8.x4.shared.b16 {%0,%1,%2,%3}, [%4];"
                             : "=r"(b[nj][0]), "=r"(b[nj][1]), "=r"(b[nj][2]), "=r"(b[nj][3])
                             : "r"(addr));
            }
#pragma unroll
            for (int mi = 0; mi < 4; mi++)
#pragma unroll
                for (int ni = 0; ni < 4; ni++) {
                    const int nj = ni >> 1, sl = ni & 1;
                    asm volatile(
                        "mma.sync.aligned.m16n8k16.row.col.f32.f16.f16.f32 "
                        "{%0,%1,%2,%3}, {%4,%5,%6,%7}, {%8,%9}, {%0,%1,%2,%3};"
                        : "+f"(acc[mi][ni][0]), "+f"(acc[mi][ni][1]),
                          "+f"(acc[mi][ni][2]), "+f"(acc[mi][ni][3])
                        : "r"(a[mi][0]), "r"(a[mi][1]), "r"(a[mi][2]), "r"(a[mi][3]),
                          "r"(b[nj][sl]), "r"(b[nj][sl + 2]));
                }
        }
    }

    // Store fp16 (no bias): lane l owns (row = mi*16 + l/4 (+8), col = ni*8 + (l%4)*2)
    const int r0 = m0 + wm + (lane >> 2);
    const int c0 = n0 + wn + (lane & 3) * 2;
#pragma unroll
    for (int mi = 0; mi < 4; mi++) {
#pragma unroll
        for (int ni = 0; ni < 4; ni++) {
            int col = c0 + ni * 8;
            uint32_t h0 = pack_half2(acc[mi][ni][0], acc[mi][ni][1]);
            uint32_t h1 = pack_half2(acc[mi][ni][2], acc[mi][ni][3]);
            *(uint32_t*)(C + (size_t)(r0 + mi * 16) * Ncols + col) = h0;
            *(uint32_t*)(C + (size_t)(r0 + mi * 16 + 8) * Ncols + col) = h1;
        }
    }
}

// ---------------------------------------------------------------------------
// Transpose + fp16 into the fused B^T buffer:
//   bt rows [0,1024)     = Wm^T        (bt[n][k] = Wm[k][n])
//   bt rows [1024,5120)  = W_top^T     (bt[1024+n][k] = W[k][n],      k<1024)
//   bt rows [5120,9216)  = W_bot^T     (bt[5120+n][k] = W[1024+k][n])
// ---------------------------------------------------------------------------
#define WM_TILES ((H_DIM / 32) * (I_DIM / 32))               // 1024
#define W_TILES  ((K2 / 32) * (N4 / 32))                     // 64*128 = 8192

__global__ __launch_bounds__(256)
void transpose_both(const float* __restrict__ W, const float* __restrict__ Wm)
{
    __shared__ float t[32][33];
    const int tx = threadIdx.x, ty = threadIdx.y;
    int bid = blockIdx.x;
    if (bid < WM_TILES) {
        int cx = bid & (H_DIM / 32 - 1), ry = bid / (H_DIM / 32);
        int r0 = ry * 32, c0 = cx * 32;
        for (int i = ty; i < 32; i += 8)
            t[i][tx] = Wm[(size_t)(r0 + i) * H_DIM + c0 + tx];
        __syncthreads();
        for (int j = ty; j < 32; j += 8)
            g_bt[(size_t)(c0 + j) * KDIM + r0 + tx] = __float2half_rn(t[tx][j]);
    } else {
        bid -= WM_TILES;
        int cx = bid & (N4 / 32 - 1), ry = bid / (N4 / 32);
        int r0 = ry * 32, c0 = cx * 32;   // r0: W row (k-dim 0-2047), c0: W col (n)
        for (int i = ty; i < 32; i += 8)
            t[i][tx] = W[(size_t)(r0 + i) * N4 + c0 + tx];
        __syncthreads();
        int base = (r0 < 1024) ? 1024 : 5120;
        int kloc = (r0 < 1024) ? r0 : (r0 - 1024);
        for (int j = ty; j < 32; j += 8)
            g_bt[(size_t)(base + c0 + j) * KDIM + kloc + tx] = __float2half_rn(t[tx][j]);
    }
}

// ---------------------------------------------------------------------------
// Activation rounding: g_axh = [fp16(x) | fp16(hx)]
// ---------------------------------------------------------------------------
__global__ __launch_bounds__(256)
void split_acts(const float* __restrict__ x, const float* __restrict__ hx)
{
    const int Q1 = (B_DIM * I_DIM) / 4;
    const int total = Q1 + (B_DIM * H_DIM) / 4;
    for (int q = blockIdx.x * blockDim.x + threadIdx.x; q < total;
         q += gridDim.x * blockDim.x) {
        if (q < Q1) {
            int r = q >> 8, c4 = q & 255;
            float4 v = ((const float4*)x)[q];
            uint2 o;
            o.x = pack_half2(v.x, v.y);
            o.y = pack_half2(v.z, v.w);
            *(uint2*)(g_axh + (size_t)r * K2 + c4 * 4) = o;
        } else {
            int j = q - Q1;
            int r = j >> 8, c4 = j & 255;
            float4 v = ((const float4*)hx)[j];
            uint2 o;
            o.x = pack_half2(v.x, v.y);
            o.y = pack_half2(v.z, v.w);
            *(uint2*)(g_axh + (size_t)r * K2 + 1024 + c4 * 4) = o;
        }
    }
}

// ---------------------------------------------------------------------------
__device__ __forceinline__ void block_reduce(float* vals, int n, float* sh, float* outp)
{
    const int lane = threadIdx.x & 31;
    const int warp = threadIdx.x >> 5;
    const int nw   = blockDim.x >> 5;
    for (int q = 0; q < n; q++) {
        float v = vals[q];
#pragma unroll
        for (int o = 16; o > 0; o >>= 1) v += __shfl_xor_sync(0xffffffffu, v, o);
        if (lane == 0) sh[warp * 8 + q] = v;
    }
    __syncthreads();
    if (warp < n) {
        float v = (lane < nw) ? sh[lane * 8 + warp] : 0.0f;
#pragma unroll
        for (int o = 16; o > 0; o >>= 1) v += __shfl_xor_sync(0xffffffffu, v, o);
        if (lane == 0) outp[warp] = v;
    }
    __syncthreads();
}

// ---------------------------------------------------------------------------
// Mega-epilogue, one CTA (1024 thr) per row:
//  attn from C1[:, :1024]+bm vs hx;  gates = attn_scale*P + Q + b;
//  4x LN + activations, cell update, cosine gate, outputs.
// ---------------------------------------------------------------------------
__global__ __launch_bounds__(1024)
void epilogue_kernel(const float* __restrict__ cx, const float* __restrict__ bm,
                     const float* __restrict__ b,  const float* __restrict__ gammas,
                     const float* __restrict__ betas, float* __restrict__ out)
{
    __shared__ float sh[32 * 8];
    __shared__ float outp[8];
    const int r = blockIdx.x;
    const int j = threadIdx.x;

    const __half* c1row = g_c1 + (size_t)r * N_A;
    const __half* c2row = g_c2 + (size_t)r * N4;

    // ---- attn = sigmoid(cos(im, hx)) ----
    float imj = __half2float(c1row[j]) + bm[j];
    float hxj = __half2float(g_axh[(size_t)r * K2 + 1024 + j]);
    float vals0[3] = {imj * hxj, imj * imj, hxj * hxj};
    block_reduce(vals0, 3, sh, outp);
    float na0 = fmaxf(sqrtf(outp[1]), 1e-6f);
    float nb0 = fmaxf(sqrtf(outp[2]), 1e-6f);
    float s = 1.0f + sigmoidf_(outp[0] / (na0 * nb0));

    // ---- gates = s*P + Q + b ----
    float v[4];
#pragma unroll
    for (int q = 0; q < 4; q++) {
        float P = __half2float(c1row[1024 + q * 1024 + j]);
        float Q = __half2float(c2row[q * 1024 + j]);
        v[q] = fmaf(s, P, Q) + b[q * 1024 + j];
    }

    float vals[8] = {v[0], v[1], v[2], v[3],
                     v[0]*v[0], v[1]*v[1], v[2]*v[2], v[3]*v[3]};
    block_reduce(vals, 8, sh, outp);

    const float invH = 1.0f / 1024.0f;
    float act[4];
#pragma unroll
    for (int q = 0; q < 4; q++) {
        float mu  = outp[q] * invH;
        float var = outp[q + 4] * invH - mu * mu;
        act[q] = (v[q] - mu) * rsqrtf(var + 1e-5f) * gammas[q * 1024 + j]
                 + betas[q * 1024 + j];
    }
    float i_g = sigmoidf_(act[0]);
    float f_g = sigmoidf_(act[1]);
    float g_g = tanhf(act[2]);
    float o_g = sigmoidf_(act[3]);

    float cxn = fmaf(f_g, cx[(size_t)r * 1024 + j], i_g * g_g);
    float hxn = o_g * tanhf(cxn);

    float vals2[3] = {hxn * cxn, hxn * hxn, cxn * cxn};
    block_reduce(vals2, 3, sh, outp);

    float na = fmaxf(sqrtf(outp[1]), 1e-6f);
    float nb = fmaxf(sqrtf(outp[2]), 1e-6f);
    float gc = sigmoidf_((outp[0] / (na * nb) + 1.0f) * 0.5f);

    out[(size_t)r * 1024 + j] = hxn * (1.0f + gc);
    out[(size_t)B_DIM * 1024 + (size_t)r * 1024 + j] = cxn;
}

// ---------------------------------------------------------------------------
extern "C" void kernel_launch(void* const* d_in, const int* in_sizes, int n_in,
                              void* d_out, int out_size)
{
    const float* x      = (const float*)d_in[0];
    const float* hx     = (const float*)d_in[1];
    const float* cx     = (const float*)d_in[2];
    const float* W      = (const float*)d_in[3];   // [2048, 4096]
    const float* b      = (const float*)d_in[4];   // [4096]
    const float* Wm     = (const float*)d_in[5];   // [1024, 1024]
    const float* bm     = (const float*)d_in[6];   // [1024]
    const float* gammas = (const float*)d_in[7];
    const float* betas  = (const float*)d_in[8];
    float* out = (float*)d_out;

    cudaFuncSetAttribute(hgemm_dual, cudaFuncAttributeMaxDynamicSharedMemorySize,
                         GEMM_SMEM);

    // (1) weight transposes + fp16 into fused B^T buffer
    transpose_both<<<WM_TILES + W_TILES, dim3(32, 8)>>>(W, Wm);

    // (2) activation fp16 rounding into [x | hx]
    split_acts<<<4096, 256>>>(x, hx);

    // (3) fused dual GEMM: C1 = x@[Wm|W_top], C2 = hx@W_bot (one launch)
    hgemm_dual<<<GRID_A + GRID_B, 256, GEMM_SMEM>>>();

    // (4) mega-epilogue: attn + gates assembly + LN + cell + cosine + outputs
    epilogue_kernel<<<B_DIM, 1024>>>(cx, bm, b, gammas, betas, out);
}

// round 12
// speedup vs baseline: 1.1385x; 1.1317x over previous
#include <cuda_runtime.h>
#include <cuda_fp16.h>
#include <math.h>
#include <cstdint>

// Problem dims (fixed by dataset)
#define B_DIM 8192
#define I_DIM 1024
#define H_DIM 1024
#define N4    4096
#define K2    2048   // I+H
#define N_A   5120   // Wm(1024) + W_top(4096) fused N for GEMM_A
#define KDIM  1024   // K for both GEMMs

// ---------------- scratch (device globals; allocation-free) ----------------
__device__ __half g_axh [(size_t)B_DIM * K2];        // [fp16(x) | fp16(hx)]
__device__ __half g_bt  [(size_t)(N_A + N4) * KDIM]; // [Wm^T; W_top^T; W_bot^T]
__device__ __half g_c1  [(size_t)B_DIM * N_A];       // x @ [Wm | W_top]
__device__ __half g_c2  [(size_t)B_DIM * N4];        // hx @ W_bot

__device__ __forceinline__ float sigmoidf_(float z) {
    return 1.0f / (1.0f + __expf(-z));
}
__device__ __forceinline__ float tanhf_(float z) {
    return 2.0f / (1.0f + __expf(-2.0f * z)) - 1.0f;
}
__device__ __forceinline__ uint32_t smem_u32(const void* p) {
    uint32_t a;
    asm("{ .reg .u64 t; cvta.to.shared.u64 t, %1; cvt.u32.u64 %0, t; }"
        : "=r"(a) : "l"(p));
    return a;
}
__device__ __forceinline__ uint32_t sw128(uint32_t off) {
    return off ^ ((off >> 3) & 0x70);
}
__device__ __forceinline__ uint32_t pack_half2(float a, float b) {
    __half2 h = __floats2half2_rn(a, b);
    return *reinterpret_cast<uint32_t*>(&h);
}

// ---------------------------------------------------------------------------
// Fused dual-GEMM (pinned engine): both sub-GEMMs K=1024, lda=2048.
//   bid <  2560 : C1[m,n] = x  @ [Wm|W_top]^T   (N=5120)
//   bid >= 2560 : C2[m,n] = hx @ W_bot^T        (N=4096)
// CTA tile 128x128, KC=64, 256 thr (8 warps, 2Mx4N warp tile 64x32),
// 3-stage cp.async, one __syncthreads per chunk. fp16 out, no bias.
// ---------------------------------------------------------------------------
#define TM 128
#define TN 128
#define KC 64
#define A_STG 16384
#define B_STG 16384
#define STG   (A_STG + B_STG)          // 32KB per stage
#define NSTAGE 3
#define GEMM_SMEM (NSTAGE * STG)       // 96KB
#define GRID_A (( N_A / TN) * (B_DIM / TM))   // 40*64 = 2560
#define GRID_B (( N4  / TN) * (B_DIM / TM))   // 32*64 = 2048

__global__ __launch_bounds__(256, 2)
void hgemm_dual()
{
    extern __shared__ char smem_raw[];
    const uint32_t SM = smem_u32(smem_raw);

    const int tid  = threadIdx.x;
    const int wid  = tid >> 5;
    const int lane = tid & 31;
    const int wm   = (wid & 1) * 64;
    const int wn   = (wid >> 1) * 32;

    int bid = blockIdx.x;
    const __half* A;  const __half* BT;  __half* C;
    int Ncols, m0, n0;
    if (bid < GRID_A) {
        int nx = bid % (N_A / TN), my = bid / (N_A / TN);
        A = g_axh;
        BT = g_bt;
        C = g_c1;  Ncols = N_A;
        m0 = my * TM;  n0 = nx * TN;
    } else {
        bid -= GRID_A;
        int nx = bid % (N4 / TN), my = bid / (N4 / TN);
        A = g_axh + 1024;
        BT = g_bt + (size_t)N_A * KDIM;
        C = g_c2;  Ncols = N4;
        m0 = my * TM;  n0 = nx * TN;
    }

    const int nc = KDIM / KC;      // 16

    auto load_chunk = [&](int c, int stage) {
        const int kk = c * KC;
        const __half* Ag = A  + (size_t)m0 * K2 + kk;
        const __half* Bg = BT + (size_t)n0 * KDIM + kk;
        const uint32_t sa = SM + stage * STG;
        const uint32_t sb = sa + A_STG;
#pragma unroll
        for (int t = 0; t < 4; t++) {
            int idx = tid + 256 * t;
            int rr = idx >> 3, ii = idx & 7;
            uint32_t off = sw128((uint32_t)(rr * 128 + ii * 16));
            asm volatile("cp.async.cg.shared.global [%0], [%1], 16;"
                         :: "r"(sa + off), "l"(Ag + (size_t)rr * K2 + ii * 8));
            asm volatile("cp.async.cg.shared.global [%0], [%1], 16;"
                         :: "r"(sb + off), "l"(Bg + (size_t)rr * KDIM + ii * 8));
        }
        asm volatile("cp.async.commit_group;" ::: "memory");
    };

    float acc[4][4][4];
#pragma unroll
    for (int mi = 0; mi < 4; mi++)
#pragma unroll
        for (int ni = 0; ni < 4; ni++)
#pragma unroll
            for (int q = 0; q < 4; q++) acc[mi][ni][q] = 0.0f;

    load_chunk(0, 0);
    load_chunk(1, 1);

    const int aRow  = wm + (lane & 15);
    const int bRow  = wn + (lane & 15);
    const int colHB = (lane >> 4) * 16;

    for (int c = 0; c < nc; c++) {
        if (c + 1 < nc) asm volatile("cp.async.wait_group 1;" ::: "memory");
        else            asm volatile("cp.async.wait_group 0;" ::: "memory");
        __syncthreads();
        if (c + 2 < nc) load_chunk(c + 2, (c + 2) % NSTAGE);

        const uint32_t sa = SM + (c % NSTAGE) * STG;
        const uint32_t sb = sa + A_STG;

#pragma unroll
        for (int ks = 0; ks < KC / 16; ks++) {
            uint32_t a[4][4], b[2][4];
#pragma unroll
            for (int mi = 0; mi < 4; mi++) {
                uint32_t addr = sa + sw128((uint32_t)((aRow + mi * 16) * 128 + ks * 32 + colHB));
                asm volatile("ldmatrix.sync.aligned.m8n8.x4.shared.b16 {%0,%1,%2,%3}, [%4];"
                             : "=r"(a[mi][0]), "=r"(a[mi][1]), "=r"(a[mi][2]), "=r"(a[mi][3])
                             : "r"(addr));
            }
#pragma unroll
            for (int nj = 0; nj < 2; nj++) {
                uint32_t addr = sb + sw128((uint32_t)((bRow + nj * 16) * 128 + ks * 32 + colHB));
                asm volatile("ldmatrix.sync.aligned.m8n8.x4.shared.b16 {%0,%1,%2,%3}, [%4];"
                             : "=r"(b[nj][0]), "=r"(b[nj][1]), "=r"(b[nj][2]), "=r"(b[nj][3])
                             : "r"(addr));
            }
#pragma unroll
            for (int mi = 0; mi < 4; mi++)
#pragma unroll
                for (int ni = 0; ni < 4; ni++) {
                    const int nj = ni >> 1, sl = ni & 1;
                    asm volatile(
                        "mma.sync.aligned.m16n8k16.row.col.f32.f16.f16.f32 "
                        "{%0,%1,%2,%3}, {%4,%5,%6,%7}, {%8,%9}, {%0,%1,%2,%3};"
                        : "+f"(acc[mi][ni][0]), "+f"(acc[mi][ni][1]),
                          "+f"(acc[mi][ni][2]), "+f"(acc[mi][ni][3])
                        : "r"(a[mi][0]), "r"(a[mi][1]), "r"(a[mi][2]), "r"(a[mi][3]),
                          "r"(b[nj][sl]), "r"(b[nj][sl + 2]));
                }
        }
    }

    const int r0 = m0 + wm + (lane >> 2);
    const int c0 = n0 + wn + (lane & 3) * 2;
#pragma unroll
    for (int mi = 0; mi < 4; mi++) {
#pragma unroll
        for (int ni = 0; ni < 4; ni++) {
            int col = c0 + ni * 8;
            uint32_t h0 = pack_half2(acc[mi][ni][0], acc[mi][ni][1]);
            uint32_t h1 = pack_half2(acc[mi][ni][2], acc[mi][ni][3]);
            *(uint32_t*)(C + (size_t)(r0 + mi * 16) * Ncols + col) = h0;
            *(uint32_t*)(C + (size_t)(r0 + mi * 16 + 8) * Ncols + col) = h1;
        }
    }
}

// ---------------------------------------------------------------------------
// Transpose + fp16 into the fused B^T buffer.
// ---------------------------------------------------------------------------
#define WM_TILES ((H_DIM / 32) * (I_DIM / 32))               // 1024
#define W_TILES  ((K2 / 32) * (N4 / 32))                     // 8192

__global__ __launch_bounds__(256)
void transpose_both(const float* __restrict__ W, const float* __restrict__ Wm)
{
    __shared__ float t[32][33];
    const int tx = threadIdx.x, ty = threadIdx.y;
    int bid = blockIdx.x;
    if (bid < WM_TILES) {
        int cx = bid & (H_DIM / 32 - 1), ry = bid / (H_DIM / 32);
        int r0 = ry * 32, c0 = cx * 32;
        for (int i = ty; i < 32; i += 8)
            t[i][tx] = Wm[(size_t)(r0 + i) * H_DIM + c0 + tx];
        __syncthreads();
        for (int j = ty; j < 32; j += 8)
            g_bt[(size_t)(c0 + j) * KDIM + r0 + tx] = __float2half_rn(t[tx][j]);
    } else {
        bid -= WM_TILES;
        int cx = bid & (N4 / 32 - 1), ry = bid / (N4 / 32);
        int r0 = ry * 32, c0 = cx * 32;
        for (int i = ty; i < 32; i += 8)
            t[i][tx] = W[(size_t)(r0 + i) * N4 + c0 + tx];
        __syncthreads();
        int base = (r0 < 1024) ? 1024 : 5120;
        int kloc = (r0 < 1024) ? r0 : (r0 - 1024);
        for (int j = ty; j < 32; j += 8)
            g_bt[(size_t)(base + c0 + j) * KDIM + kloc + tx] = __float2half_rn(t[tx][j]);
    }
}

// ---------------------------------------------------------------------------
// Activation rounding: g_axh = [fp16(x) | fp16(hx)]
// ---------------------------------------------------------------------------
__global__ __launch_bounds__(256)
void split_acts(const float* __restrict__ x, const float* __restrict__ hx)
{
    const int Q1 = (B_DIM * I_DIM) / 4;
    const int total = Q1 + (B_DIM * H_DIM) / 4;
    for (int q = blockIdx.x * blockDim.x + threadIdx.x; q < total;
         q += gridDim.x * blockDim.x) {
        if (q < Q1) {
            int r = q >> 8, c4 = q & 255;
            float4 v = ((const float4*)x)[q];
            uint2 o;
            o.x = pack_half2(v.x, v.y);
            o.y = pack_half2(v.z, v.w);
            *(uint2*)(g_axh + (size_t)r * K2 + c4 * 4) = o;
        } else {
            int j = q - Q1;
            int r = j >> 8, c4 = j & 255;
            float4 v = ((const float4*)hx)[j];
            uint2 o;
            o.x = pack_half2(v.x, v.y);
            o.y = pack_half2(v.z, v.w);
            *(uint2*)(g_axh + (size_t)r * K2 + 1024 + c4 * 4) = o;
        }
    }
}

// ---------------------------------------------------------------------------
__device__ __forceinline__ void block_reduce(float* vals, int n, float* sh, float* outp)
{
    const int lane = threadIdx.x & 31;
    const int warp = threadIdx.x >> 5;
    const int nw   = blockDim.x >> 5;
    for (int q = 0; q < n; q++) {
        float v = vals[q];
#pragma unroll
        for (int o = 16; o > 0; o >>= 1) v += __shfl_xor_sync(0xffffffffu, v, o);
        if (lane == 0) sh[warp * 8 + q] = v;
    }
    __syncthreads();
    if (warp < n) {
        float v = (lane < nw) ? sh[lane * 8 + warp] : 0.0f;
#pragma unroll
        for (int o = 16; o > 0; o >>= 1) v += __shfl_xor_sync(0xffffffffu, v, o);
        if (lane == 0) outp[warp] = v;
    }
    __syncthreads();
}

// ---------------------------------------------------------------------------
// Mega-epilogue v2: 256 threads/CTA, 4 elements/thread, vectorized loads,
// per-thread pre-accumulation before reduces, MUFU tanh/sigmoid.
// ---------------------------------------------------------------------------
__global__ __launch_bounds__(256)
void epilogue_kernel(const float* __restrict__ cx, const float* __restrict__ bm,
                     const float* __restrict__ b,  const float* __restrict__ gammas,
                     const float* __restrict__ betas, float* __restrict__ out)
{
    __shared__ float sh[32 * 8];
    __shared__ float outp[8];
    const int r = blockIdx.x;
    const int t = threadIdx.x;
    const int e = 4 * t;

    const __half* c1row = g_c1 + (size_t)r * N_A;
    const __half* c2row = g_c2 + (size_t)r * N4;

    // ---- phase 1: attn = sigmoid(cos(im, hx)) ----
    float hxv[4];
    {
        uint2 pv = *(const uint2*)(c1row + e);
        float2 p01 = __half22float2(*reinterpret_cast<__half2*>(&pv.x));
        float2 p23 = __half22float2(*reinterpret_cast<__half2*>(&pv.y));
        float4 bm4 = *(const float4*)(bm + e);
        uint2 hv = *(const uint2*)(g_axh + (size_t)r * K2 + 1024 + e);
        float2 h01 = __half22float2(*reinterpret_cast<__half2*>(&hv.x));
        float2 h23 = __half22float2(*reinterpret_cast<__half2*>(&hv.y));
        float im[4] = {p01.x + bm4.x, p01.y + bm4.y, p23.x + bm4.z, p23.y + bm4.w};
        hxv[0] = h01.x; hxv[1] = h01.y; hxv[2] = h23.x; hxv[3] = h23.y;
        float dot = 0, s1 = 0, s2 = 0;
#pragma unroll
        for (int k = 0; k < 4; k++) {
            dot = fmaf(im[k], hxv[k], dot);
            s1  = fmaf(im[k], im[k], s1);
            s2  = fmaf(hxv[k], hxv[k], s2);
        }
        float v0[3] = {dot, s1, s2};
        block_reduce(v0, 3, sh, outp);
    }
    float na0 = fmaxf(sqrtf(outp[1]), 1e-6f);
    float nb0 = fmaxf(sqrtf(outp[2]), 1e-6f);
    float s = 1.0f + sigmoidf_(outp[0] / (na0 * nb0));

    // ---- phase 2: gates = s*P + Q + b;  row sums & sumsq ----
    float v[4][4];
    float vals[8];
#pragma unroll
    for (int q = 0; q < 8; q++) vals[q] = 0.0f;
#pragma unroll
    for (int q = 0; q < 4; q++) {
        uint2 pv = *(const uint2*)(c1row + 1024 + q * 1024 + e);
        uint2 qv = *(const uint2*)(c2row + q * 1024 + e);
        float2 p01 = __half22float2(*reinterpret_cast<__half2*>(&pv.x));
        float2 p23 = __half22float2(*reinterpret_cast<__half2*>(&pv.y));
        float2 q01 = __half22float2(*reinterpret_cast<__half2*>(&qv.x));
        float2 q23 = __half22float2(*reinterpret_cast<__half2*>(&qv.y));
        float4 b4 = *(const float4*)(b + q * 1024 + e);
        v[q][0] = fmaf(s, p01.x, q01.x) + b4.x;
        v[q][1] = fmaf(s, p01.y, q01.y) + b4.y;
        v[q][2] = fmaf(s, p23.x, q23.x) + b4.z;
        v[q][3] = fmaf(s, p23.y, q23.y) + b4.w;
#pragma unroll
        for (int k = 0; k < 4; k++) {
            vals[q]     += v[q][k];
            vals[q + 4]  = fmaf(v[q][k], v[q][k], vals[q + 4]);
        }
    }
    block_reduce(vals, 8, sh, outp);

    const float invH = 1.0f / 1024.0f;
    float mu[4], rs[4];
#pragma unroll
    for (int q = 0; q < 4; q++) {
        mu[q] = outp[q] * invH;
        float var = outp[q + 4] * invH - mu[q] * mu[q];
        rs[q] = rsqrtf(var + 1e-5f);
    }

    // ---- phase 3: LN + activations + cell update ----
    float4 ga[4], be[4];
#pragma unroll
    for (int q = 0; q < 4; q++) {
        ga[q] = *(const float4*)(gammas + q * 1024 + e);
        be[q] = *(const float4*)(betas  + q * 1024 + e);
    }
    float4 cx4 = *(const float4*)(cx + (size_t)r * 1024 + e);
    const float cxe[4] = {cx4.x, cx4.y, cx4.z, cx4.w};

    float hxn[4], cxn[4];
    float d2 = 0, h2 = 0, c2 = 0;
#pragma unroll
    for (int k = 0; k < 4; k++) {
        const float gaq[4] = {((const float*)&ga[0])[k], ((const float*)&ga[1])[k],
                              ((const float*)&ga[2])[k], ((const float*)&ga[3])[k]};
        const float beq[4] = {((const float*)&be[0])[k], ((const float*)&be[1])[k],
                              ((const float*)&be[2])[k], ((const float*)&be[3])[k]};
        float a0 = (v[0][k] - mu[0]) * rs[0] * gaq[0] + beq[0];
        float a1 = (v[1][k] - mu[1]) * rs[1] * gaq[1] + beq[1];
        float a2 = (v[2][k] - mu[2]) * rs[2] * gaq[2] + beq[2];
        float a3 = (v[3][k] - mu[3]) * rs[3] * gaq[3] + beq[3];
        float i_g = sigmoidf_(a0);
        float f_g = sigmoidf_(a1);
        float g_g = tanhf_(a2);
        float o_g = sigmoidf_(a3);
        float cn = fmaf(f_g, cxe[k], i_g * g_g);
        float hn = o_g * tanhf_(cn);
        cxn[k] = cn; hxn[k] = hn;
        d2 = fmaf(hn, cn, d2);
        h2 = fmaf(hn, hn, h2);
        c2 = fmaf(cn, cn, c2);
    }
    float vals2[3] = {d2, h2, c2};
    block_reduce(vals2, 3, sh, outp);

    float na = fmaxf(sqrtf(outp[1]), 1e-6f);
    float nb = fmaxf(sqrtf(outp[2]), 1e-6f);
    float gc = sigmoidf_((outp[0] / (na * nb) + 1.0f) * 0.5f);
    float gs = 1.0f + gc;

    float4 o1 = make_float4(hxn[0] * gs, hxn[1] * gs, hxn[2] * gs, hxn[3] * gs);
    float4 o2 = make_float4(cxn[0], cxn[1], cxn[2], cxn[3]);
    *(float4*)(out + (size_t)r * 1024 + e) = o1;
    *(float4*)(out + (size_t)B_DIM * 1024 + (size_t)r * 1024 + e) = o2;
}

// ---------------------------------------------------------------------------
extern "C" void kernel_launch(void* const* d_in, const int* in_sizes, int n_in,
                              void* d_out, int out_size)
{
    const float* x      = (const float*)d_in[0];
    const float* hx     = (const float*)d_in[1];
    const float* cx     = (const float*)d_in[2];
    const float* W      = (const float*)d_in[3];   // [2048, 4096]
    const float* b      = (const float*)d_in[4];   // [4096]
    const float* Wm     = (const float*)d_in[5];   // [1024, 1024]
    const float* bm     = (const float*)d_in[6];   // [1024]
    const float* gammas = (const float*)d_in[7];
    const float* betas  = (const float*)d_in[8];
    float* out = (float*)d_out;

    cudaFuncSetAttribute(hgemm_dual, cudaFuncAttributeMaxDynamicSharedMemorySize,
                         GEMM_SMEM);

    // (1) weight transposes + fp16 into fused B^T buffer
    transpose_both<<<WM_TILES + W_TILES, dim3(32, 8)>>>(W, Wm);

    // (2) activation fp16 rounding into [x | hx]
    split_acts<<<4096, 256>>>(x, hx);

    // (3) fused dual GEMM: C1 = x@[Wm|W_top], C2 = hx@W_bot (one launch)
    hgemm_dual<<<GRID_A + GRID_B, 256, GEMM_SMEM>>>();

    // (4) mega-epilogue v2
    epilogue_kernel<<<B_DIM, 256>>>(cx, bm, b, gammas, betas, out);
}

// round 13
// speedup vs baseline: 1.1851x; 1.0409x over previous
#include <cuda_runtime.h>
#include <cuda_fp16.h>
#include <math.h>
#include <cstdint>

// Problem dims (fixed by dataset)
#define B_DIM 8192
#define I_DIM 1024
#define H_DIM 1024
#define N4    4096
#define K2    2048   // I+H
#define N_A   5120   // Wm(1024) + W_top(4096) fused N for GEMM_A
#define KDIM  1024   // K for both GEMMs

// ---------------- scratch (device globals; allocation-free) ----------------
__device__ __half g_axh [(size_t)B_DIM * K2];        // [fp16(x) | fp16(hx)]
__device__ __half g_bt  [(size_t)(N_A + N4) * KDIM]; // [Wm^T; W_top^T; W_bot^T]
__device__ __half g_c1  [(size_t)B_DIM * N_A];       // x @ [Wm | W_top]
__device__ __half g_c2  [(size_t)B_DIM * N4];        // hx @ W_bot

__device__ __forceinline__ float sigmoidf_(float z) {
    return 1.0f / (1.0f + __expf(-z));
}
__device__ __forceinline__ float tanhf_(float z) {
    return 2.0f / (1.0f + __expf(-2.0f * z)) - 1.0f;
}
__device__ __forceinline__ uint32_t smem_u32(const void* p) {
    uint32_t a;
    asm("{ .reg .u64 t; cvta.to.shared.u64 t, %1; cvt.u32.u64 %0, t; }"
        : "=r"(a) : "l"(p));
    return a;
}
__device__ __forceinline__ uint32_t sw128(uint32_t off) {
    return off ^ ((off >> 3) & 0x70);
}
__device__ __forceinline__ uint32_t pack_half2(float a, float b) {
    __half2 h = __floats2half2_rn(a, b);
    return *reinterpret_cast<uint32_t*>(&h);
}

// ---------------------------------------------------------------------------
// Fused dual-GEMM (pinned engine): both sub-GEMMs K=1024, lda=2048.
//   bid <  2560 : C1[m,n] = x  @ [Wm|W_top]^T   (N=5120)
//   bid >= 2560 : C2[m,n] = hx @ W_bot^T        (N=4096)
// CTA tile 128x128, KC=64, 256 thr (8 warps, 2Mx4N warp tile 64x32),
// 3-stage cp.async, one __syncthreads per chunk. fp16 out, no bias.
// ---------------------------------------------------------------------------
#define TM 128
#define TN 128
#define KC 64
#define A_STG 16384
#define B_STG 16384
#define STG   (A_STG + B_STG)          // 32KB per stage
#define NSTAGE 3
#define GEMM_SMEM (NSTAGE * STG)       // 96KB
#define GRID_A (( N_A / TN) * (B_DIM / TM))   // 40*64 = 2560
#define GRID_B (( N4  / TN) * (B_DIM / TM))   // 32*64 = 2048

__global__ __launch_bounds__(256, 2)
void hgemm_dual()
{
    extern __shared__ char smem_raw[];
    const uint32_t SM = smem_u32(smem_raw);

    const int tid  = threadIdx.x;
    const int wid  = tid >> 5;
    const int lane = tid & 31;
    const int wm   = (wid & 1) * 64;
    const int wn   = (wid >> 1) * 32;

    int bid = blockIdx.x;
    const __half* A;  const __half* BT;  __half* C;
    int Ncols, m0, n0;
    if (bid < GRID_A) {
        int nx = bid % (N_A / TN), my = bid / (N_A / TN);
        A = g_axh;
        BT = g_bt;
        C = g_c1;  Ncols = N_A;
        m0 = my * TM;  n0 = nx * TN;
    } else {
        bid -= GRID_A;
        int nx = bid % (N4 / TN), my = bid / (N4 / TN);
        A = g_axh + 1024;
        BT = g_bt + (size_t)N_A * KDIM;
        C = g_c2;  Ncols = N4;
        m0 = my * TM;  n0 = nx * TN;
    }

    const int nc = KDIM / KC;      // 16

    auto load_chunk = [&](int c, int stage) {
        const int kk = c * KC;
        const __half* Ag = A  + (size_t)m0 * K2 + kk;
        const __half* Bg = BT + (size_t)n0 * KDIM + kk;
        const uint32_t sa = SM + stage * STG;
        const uint32_t sb = sa + A_STG;
#pragma unroll
        for (int t = 0; t < 4; t++) {
            int idx = tid + 256 * t;
            int rr = idx >> 3, ii = idx & 7;
            uint32_t off = sw128((uint32_t)(rr * 128 + ii * 16));
            asm volatile("cp.async.cg.shared.global [%0], [%1], 16;"
                         :: "r"(sa + off), "l"(Ag + (size_t)rr * K2 + ii * 8));
            asm volatile("cp.async.cg.shared.global [%0], [%1], 16;"
                         :: "r"(sb + off), "l"(Bg + (size_t)rr * KDIM + ii * 8));
        }
        asm volatile("cp.async.commit_group;" ::: "memory");
    };

    float acc[4][4][4];
#pragma unroll
    for (int mi = 0; mi < 4; mi++)
#pragma unroll
        for (int ni = 0; ni < 4; ni++)
#pragma unroll
            for (int q = 0; q < 4; q++) acc[mi][ni][q] = 0.0f;

    load_chunk(0, 0);
    load_chunk(1, 1);

    const int aRow  = wm + (lane & 15);
    const int bRow  = wn + (lane & 15);
    const int colHB = (lane >> 4) * 16;

    for (int c = 0; c < nc; c++) {
        if (c + 1 < nc) asm volatile("cp.async.wait_group 1;" ::: "memory");
        else            asm volatile("cp.async.wait_group 0;" ::: "memory");
        __syncthreads();
        if (c + 2 < nc) load_chunk(c + 2, (c + 2) % NSTAGE);

        const uint32_t sa = SM + (c % NSTAGE) * STG;
        const uint32_t sb = sa + A_STG;

#pragma unroll
        for (int ks = 0; ks < KC / 16; ks++) {
            uint32_t a[4][4], b[2][4];
#pragma unroll
            for (int mi = 0; mi < 4; mi++) {
                uint32_t addr = sa + sw128((uint32_t)((aRow + mi * 16) * 128 + ks * 32 + colHB));
                asm volatile("ldmatrix.sync.aligned.m8n8.x4.shared.b16 {%0,%1,%2,%3}, [%4];"
                             : "=r"(a[mi][0]), "=r"(a[mi][1]), "=r"(a[mi][2]), "=r"(a[mi][3])
                             : "r"(addr));
            }
#pragma unroll
            for (int nj = 0; nj < 2; nj++) {
                uint32_t addr = sb + sw128((uint32_t)((bRow + nj * 16) * 128 + ks * 32 + colHB));
                asm volatile("ldmatrix.sync.aligned.m8n8.x4.shared.b16 {%0,%1,%2,%3}, [%4];"
                             : "=r"(b[nj][0]), "=r"(b[nj][1]), "=r"(b[nj][2]), "=r"(b[nj][3])
                             : "r"(addr));
            }
#pragma unroll
            for (int mi = 0; mi < 4; mi++)
#pragma unroll
                for (int ni = 0; ni < 4; ni++) {
                    const int nj = ni >> 1, sl = ni & 1;
                    asm volatile(
                        "mma.sync.aligned.m16n8k16.row.col.f32.f16.f16.f32 "
                        "{%0,%1,%2,%3}, {%4,%5,%6,%7}, {%8,%9}, {%0,%1,%2,%3};"
                        : "+f"(acc[mi][ni][0]), "+f"(acc[mi][ni][1]),
                          "+f"(acc[mi][ni][2]), "+f"(acc[mi][ni][3])
                        : "r"(a[mi][0]), "r"(a[mi][1]), "r"(a[mi][2]), "r"(a[mi][3]),
                          "r"(b[nj][sl]), "r"(b[nj][sl + 2]));
                }
        }
    }

    const int r0 = m0 + wm + (lane >> 2);
    const int c0 = n0 + wn + (lane & 3) * 2;
#pragma unroll
    for (int mi = 0; mi < 4; mi++) {
#pragma unroll
        for (int ni = 0; ni < 4; ni++) {
            int col = c0 + ni * 8;
            uint32_t h0 = pack_half2(acc[mi][ni][0], acc[mi][ni][1]);
            uint32_t h1 = pack_half2(acc[mi][ni][2], acc[mi][ni][3]);
            *(uint32_t*)(C + (size_t)(r0 + mi * 16) * Ncols + col) = h0;
            *(uint32_t*)(C + (size_t)(r0 + mi * 16 + 8) * Ncols + col) = h1;
        }
    }
}

// ---------------------------------------------------------------------------
// Merged prep: weight transposes (fp16) AND activation rounding, ONE launch.
//   bid < WM_TILES                 : Wm transpose tile
//   bid < WM_TILES + W_TILES       : W transpose tile
//   else                           : activation split (grid-stride over both)
// ---------------------------------------------------------------------------
#define WM_TILES ((H_DIM / 32) * (I_DIM / 32))               // 1024
#define W_TILES  ((K2 / 32) * (N4 / 32))                     // 8192
#define ACT_BLKS 2048

__global__ __launch_bounds__(256)
void prep_all(const float* __restrict__ W, const float* __restrict__ Wm,
              const float* __restrict__ x, const float* __restrict__ hx)
{
    __shared__ float t[32][33];
    int bid = blockIdx.x;
    if (bid < WM_TILES + W_TILES) {
        const int tx = threadIdx.x & 31, ty = threadIdx.x >> 5;
        if (bid < WM_TILES) {
            int cx = bid & (H_DIM / 32 - 1), ry = bid / (H_DIM / 32);
            int r0 = ry * 32, c0 = cx * 32;
            for (int i = ty; i < 32; i += 8)
                t[i][tx] = Wm[(size_t)(r0 + i) * H_DIM + c0 + tx];
            __syncthreads();
            for (int j = ty; j < 32; j += 8)
                g_bt[(size_t)(c0 + j) * KDIM + r0 + tx] = __float2half_rn(t[tx][j]);
        } else {
            bid -= WM_TILES;
            int cx = bid & (N4 / 32 - 1), ry = bid / (N4 / 32);
            int r0 = ry * 32, c0 = cx * 32;
            for (int i = ty; i < 32; i += 8)
                t[i][tx] = W[(size_t)(r0 + i) * N4 + c0 + tx];
            __syncthreads();
            int base = (r0 < 1024) ? 1024 : 5120;
            int kloc = (r0 < 1024) ? r0 : (r0 - 1024);
            for (int j = ty; j < 32; j += 8)
                g_bt[(size_t)(base + c0 + j) * KDIM + kloc + tx] = __float2half_rn(t[tx][j]);
        }
    } else {
        bid -= WM_TILES + W_TILES;
        const int Q1 = (B_DIM * I_DIM) / 4;
        const int total = Q1 + (B_DIM * H_DIM) / 4;
        for (int q = bid * 256 + threadIdx.x; q < total; q += ACT_BLKS * 256) {
            if (q < Q1) {
                int r = q >> 8, c4 = q & 255;
                float4 v = ((const float4*)x)[q];
                uint2 o;
                o.x = pack_half2(v.x, v.y);
                o.y = pack_half2(v.z, v.w);
                *(uint2*)(g_axh + (size_t)r * K2 + c4 * 4) = o;
            } else {
                int j = q - Q1;
                int r = j >> 8, c4 = j & 255;
                float4 v = ((const float4*)hx)[j];
                uint2 o;
                o.x = pack_half2(v.x, v.y);
                o.y = pack_half2(v.z, v.w);
                *(uint2*)(g_axh + (size_t)r * K2 + 1024 + c4 * 4) = o;
            }
        }
    }
}

// ---------------------------------------------------------------------------
__device__ __forceinline__ void block_reduce(float* vals, int n, float* sh, float* outp)
{
    const int lane = threadIdx.x & 31;
    const int warp = threadIdx.x >> 5;
    const int nw   = blockDim.x >> 5;
    for (int q = 0; q < n; q++) {
        float v = vals[q];
#pragma unroll
        for (int o = 16; o > 0; o >>= 1) v += __shfl_xor_sync(0xffffffffu, v, o);
        if (lane == 0) sh[warp * 8 + q] = v;
    }
    __syncthreads();
    if (warp < n) {
        float v = (lane < nw) ? sh[lane * 8 + warp] : 0.0f;
#pragma unroll
        for (int o = 16; o > 0; o >>= 1) v += __shfl_xor_sync(0xffffffffu, v, o);
        if (lane == 0) outp[warp] = v;
    }
    __syncthreads();
}

// ---------------------------------------------------------------------------
// Mega-epilogue v3: 256 thr/CTA, 4 elem/thread, register-dieted for occ>=4.
// LN affine folded in a transient q-loop so gamma/beta never persist.
// ---------------------------------------------------------------------------
__global__ __launch_bounds__(256, 4)
void epilogue_kernel(const float* __restrict__ cx, const float* __restrict__ bm,
                     const float* __restrict__ b,  const float* __restrict__ gammas,
                     const float* __restrict__ betas, float* __restrict__ out)
{
    __shared__ float sh[32 * 8];
    __shared__ float outp[8];
    const int r = blockIdx.x;
    const int t = threadIdx.x;
    const int e = 4 * t;

    const __half* c1row = g_c1 + (size_t)r * N_A;
    const __half* c2row = g_c2 + (size_t)r * N4;

    // ---- phase 1: attn = sigmoid(cos(im, hx)) ----
    {
        uint2 pv = *(const uint2*)(c1row + e);
        float2 p01 = __half22float2(*reinterpret_cast<__half2*>(&pv.x));
        float2 p23 = __half22float2(*reinterpret_cast<__half2*>(&pv.y));
        float4 bm4 = *(const float4*)(bm + e);
        uint2 hv = *(const uint2*)(g_axh + (size_t)r * K2 + 1024 + e);
        float2 h01 = __half22float2(*reinterpret_cast<__half2*>(&hv.x));
        float2 h23 = __half22float2(*reinterpret_cast<__half2*>(&hv.y));
        float im[4] = {p01.x + bm4.x, p01.y + bm4.y, p23.x + bm4.z, p23.y + bm4.w};
        float hxv[4] = {h01.x, h01.y, h23.x, h23.y};
        float dot = 0, s1 = 0, s2 = 0;
#pragma unroll
        for (int k = 0; k < 4; k++) {
            dot = fmaf(im[k], hxv[k], dot);
            s1  = fmaf(im[k], im[k], s1);
            s2  = fmaf(hxv[k], hxv[k], s2);
        }
        float v0[3] = {dot, s1, s2};
        block_reduce(v0, 3, sh, outp);
    }
    float na0 = fmaxf(sqrtf(outp[1]), 1e-6f);
    float nb0 = fmaxf(sqrtf(outp[2]), 1e-6f);
    float s = 1.0f + sigmoidf_(outp[0] / (na0 * nb0));

    // ---- phase 2: gates = s*P + Q + b;  row sums & sumsq ----
    float v[4][4];
    float vals[8];
#pragma unroll
    for (int q = 0; q < 8; q++) vals[q] = 0.0f;
#pragma unroll
    for (int q = 0; q < 4; q++) {
        uint2 pv = *(const uint2*)(c1row + 1024 + q * 1024 + e);
        uint2 qv = *(const uint2*)(c2row + q * 1024 + e);
        float2 p01 = __half22float2(*reinterpret_cast<__half2*>(&pv.x));
        float2 p23 = __half22float2(*reinterpret_cast<__half2*>(&pv.y));
        float2 q01 = __half22float2(*reinterpret_cast<__half2*>(&qv.x));
        float2 q23 = __half22float2(*reinterpret_cast<__half2*>(&qv.y));
        float4 b4 = *(const float4*)(b + q * 1024 + e);
        v[q][0] = fmaf(s, p01.x, q01.x) + b4.x;
        v[q][1] = fmaf(s, p01.y, q01.y) + b4.y;
        v[q][2] = fmaf(s, p23.x, q23.x) + b4.z;
        v[q][3] = fmaf(s, p23.y, q23.y) + b4.w;
#pragma unroll
        for (int k = 0; k < 4; k++) {
            vals[q]     += v[q][k];
            vals[q + 4]  = fmaf(v[q][k], v[q][k], vals[q + 4]);
        }
    }
    block_reduce(vals, 8, sh, outp);

    // ---- fold LN affine into v in place (gamma/beta transient) ----
    const float invH = 1.0f / 1024.0f;
#pragma unroll
    for (int q = 0; q < 4; q++) {
        float mu = outp[q] * invH;
        float var = outp[q + 4] * invH - mu * mu;
        float rs = rsqrtf(var + 1e-5f);
        float4 ga = *(const float4*)(gammas + q * 1024 + e);
        float4 be = *(const float4*)(betas  + q * 1024 + e);
        v[q][0] = (v[q][0] - mu) * rs * ga.x + be.x;
        v[q][1] = (v[q][1] - mu) * rs * ga.y + be.y;
        v[q][2] = (v[q][2] - mu) * rs * ga.z + be.z;
        v[q][3] = (v[q][3] - mu) * rs * ga.w + be.w;
    }

    // ---- phase 3: activations + cell update ----
    float4 cx4 = *(const float4*)(cx + (size_t)r * 1024 + e);
    const float cxe[4] = {cx4.x, cx4.y, cx4.z, cx4.w};

    float hxn[4], cxn[4];
    float d2 = 0, h2 = 0, c2 = 0;
#pragma unroll
    for (int k = 0; k < 4; k++) {
        float i_g = sigmoidf_(v[0][k]);
        float f_g = sigmoidf_(v[1][k]);
        float g_g = tanhf_(v[2][k]);
        float o_g = sigmoidf_(v[3][k]);
        float cn = fmaf(f_g, cxe[k], i_g * g_g);
        float hn = o_g * tanhf_(cn);
        cxn[k] = cn; hxn[k] = hn;
        d2 = fmaf(hn, cn, d2);
        h2 = fmaf(hn, hn, h2);
        c2 = fmaf(cn, cn, c2);
    }
    float vals2[3] = {d2, h2, c2};
    block_reduce(vals2, 3, sh, outp);

    float na = fmaxf(sqrtf(outp[1]), 1e-6f);
    float nb = fmaxf(sqrtf(outp[2]), 1e-6f);
    float gc = sigmoidf_((outp[0] / (na * nb) + 1.0f) * 0.5f);
    float gs = 1.0f + gc;

    float4 o1 = make_float4(hxn[0] * gs, hxn[1] * gs, hxn[2] * gs, hxn[3] * gs);
    float4 o2 = make_float4(cxn[0], cxn[1], cxn[2], cxn[3]);
    *(float4*)(out + (size_t)r * 1024 + e) = o1;
    *(float4*)(out + (size_t)B_DIM * 1024 + (size_t)r * 1024 + e) = o2;
}

// ---------------------------------------------------------------------------
extern "C" void kernel_launch(void* const* d_in, const int* in_sizes, int n_in,
                              void* d_out, int out_size)
{
    const float* x      = (const float*)d_in[0];
    const float* hx     = (const float*)d_in[1];
    const float* cx     = (const float*)d_in[2];
    const float* W      = (const float*)d_in[3];   // [2048, 4096]
    const float* b      = (const float*)d_in[4];   // [4096]
    const float* Wm     = (const float*)d_in[5];   // [1024, 1024]
    const float* bm     = (const float*)d_in[6];   // [1024]
    const float* gammas = (const float*)d_in[7];
    const float* betas  = (const float*)d_in[8];
    float* out = (float*)d_out;

    cudaFuncSetAttribute(hgemm_dual, cudaFuncAttributeMaxDynamicSharedMemorySize,
                         GEMM_SMEM);

    // (1) merged prep: transposes + activation rounding (one launch)
    prep_all<<<WM_TILES + W_TILES + ACT_BLKS, 256>>>(W, Wm, x, hx);

    // (2) fused dual GEMM: C1 = x@[Wm|W_top], C2 = hx@W_bot (one launch)
    hgemm_dual<<<GRID_A + GRID_B, 256, GEMM_SMEM>>>();

    // (3) mega-epilogue v3
    epilogue_kernel<<<B_DIM, 256>>>(cx, bm, b, gammas, betas, out);
}